// round 2
// baseline (speedup 1.0000x reference)
#include <cuda_runtime.h>
#include <cstdint>
#include <cstddef>

#define BATCH 4
#define SEQ   1024
#define DMODEL 1024
#define NH    16
#define HD    64

// ---------------- scratch (device globals: no runtime allocation) ----------
__device__ float g_xn[BATCH*SEQ*DMODEL];   // layernormed input, fp32
__device__ float g_q[BATCH*SEQ*DMODEL];    // (B,H,S,64)
__device__ float g_k[BATCH*SEQ*DMODEL];
__device__ float g_v[BATCH*SEQ*DMODEL];

// round-to-nearest tf32 (kills truncation bias; keeps rel err ~2.4e-4)
__device__ __forceinline__ float tf32r(float f){
    unsigned u; asm("cvt.rna.tf32.f32 %0, %1;" : "=r"(u) : "f"(f));
    return __uint_as_float(u);
}

#define MMA_TF32(d, a, b_) \
  asm volatile("mma.sync.aligned.m16n8k8.row.col.f32.tf32.tf32.f32 " \
    "{%0,%1,%2,%3},{%4,%5,%6,%7},{%8,%9},{%0,%1,%2,%3};" \
    : "+f"((d)[0]),"+f"((d)[1]),"+f"((d)[2]),"+f"((d)[3]) \
    : "r"((a)[0]),"r"((a)[1]),"r"((a)[2]),"r"((a)[3]),"r"((b_)[0]),"r"((b_)[1]))

// ---------------- Kernel 1: LayerNorm (fp32, exact) ------------------------
__global__ void __launch_bounds__(256) ln_kernel(const float* __restrict__ x,
    const float* __restrict__ gamma, const float* __restrict__ beta)
{
    int row = blockIdx.x;
    int tid = threadIdx.x, lane = tid & 31, wid = tid >> 5;
    const float4* xr = (const float4*)(x + (size_t)row * DMODEL);
    float4 v = xr[tid];
    float s  = v.x + v.y + v.z + v.w;
    float sq = v.x*v.x + v.y*v.y + v.z*v.z + v.w*v.w;
    #pragma unroll
    for (int o = 16; o > 0; o >>= 1){
        s  += __shfl_xor_sync(0xffffffffu, s,  o);
        sq += __shfl_xor_sync(0xffffffffu, sq, o);
    }
    __shared__ float ws[8], wq[8], stat[2];
    if (lane == 0){ ws[wid] = s; wq[wid] = sq; }
    __syncthreads();
    if (wid == 0){
        float a = (lane < 8) ? ws[lane] : 0.f;
        float q = (lane < 8) ? wq[lane] : 0.f;
        #pragma unroll
        for (int o = 4; o > 0; o >>= 1){
            a += __shfl_xor_sync(0xffffffffu, a, o);
            q += __shfl_xor_sync(0xffffffffu, q, o);
        }
        if (lane == 0){
            float mean = a * (1.0f / DMODEL);
            float var  = q * (1.0f / DMODEL) - mean * mean;
            stat[0] = mean; stat[1] = rsqrtf(var + 1e-5f);
        }
    }
    __syncthreads();
    float mean = stat[0], rstd = stat[1];
    float4 g  = ((const float4*)gamma)[tid];
    float4 be = ((const float4*)beta)[tid];
    float4 y;
    y.x = (v.x - mean) * rstd * g.x + be.x;
    y.y = (v.y - mean) * rstd * g.y + be.y;
    y.z = (v.z - mean) * rstd * g.z + be.z;
    y.w = (v.w - mean) * rstd * g.w + be.w;
    ((float4*)(g_xn + (size_t)row * DMODEL))[tid] = y;
}

// ---------------- Kernel 2: QKV projection GEMM (tf32 mma) ------------------
// C(4096 x 3072) = xn(4096x1024) @ [Wq|Wk|Wv], 128x128x32 tiles, 256 thr.
// Output scattered to (B,H,S,64) layout.
__global__ void __launch_bounds__(256) proj_kernel(
    const float* __restrict__ Wq, const float* __restrict__ bq,
    const float* __restrict__ Wk, const float* __restrict__ bk,
    const float* __restrict__ Wv, const float* __restrict__ bv)
{
    __shared__ float As[128*36];   // stride 36 -> (4m+k) bank-conflict-free
    __shared__ float Bs[32*136];   // stride 136 -> (8k+n) conflict-free

    int m0 = blockIdx.x * 128;
    int by = blockIdx.y;
    int wsel = by >> 3;
    int n0 = (by & 7) * 128;
    const float* W    = (wsel == 0) ? Wq : (wsel == 1) ? Wk : Wv;
    const float* bias = (wsel == 0) ? bq : (wsel == 1) ? bk : bv;
    float* out        = (wsel == 0) ? g_q : (wsel == 1) ? g_k : g_v;

    int tid = threadIdx.x, lane = tid & 31, wid = tid >> 5;
    int gid = lane >> 2, tig = lane & 3;
    int wr = wid >> 2, wc = wid & 3;     // warp tile: 64 rows x 32 cols

    float acc[4][4][4];
    #pragma unroll
    for (int i=0;i<4;i++)
      #pragma unroll
      for (int j=0;j<4;j++)
        #pragma unroll
        for (int r=0;r<4;r++) acc[i][j][r] = 0.f;

    for (int k0 = 0; k0 < 1024; k0 += 32){
        __syncthreads();
        #pragma unroll
        for (int s = 0; s < 4; s++){                 // A: 128x32
            int idx = tid + 256*s;
            int r = idx >> 3, c4 = idx & 7;
            float4 v = *(const float4*)(g_xn + (size_t)(m0 + r)*1024 + k0 + c4*4);
            float* d = &As[r*36 + c4*4];
            d[0]=tf32r(v.x); d[1]=tf32r(v.y); d[2]=tf32r(v.z); d[3]=tf32r(v.w);
        }
        #pragma unroll
        for (int s = 0; s < 4; s++){                 // B: 32x128
            int idx = tid + 256*s;
            int r = idx >> 5, c4 = idx & 31;
            float4 v = *(const float4*)(W + (size_t)(k0 + r)*1024 + n0 + c4*4);
            float* d = &Bs[r*136 + c4*4];
            d[0]=tf32r(v.x); d[1]=tf32r(v.y); d[2]=tf32r(v.z); d[3]=tf32r(v.w);
        }
        __syncthreads();
        #pragma unroll
        for (int ks = 0; ks < 32; ks += 8){
            unsigned a[4][4], bfr[4][2];
            #pragma unroll
            for (int i=0;i<4;i++){
                int m = wr*64 + i*16 + gid;
                a[i][0] = __float_as_uint(As[m*36     + ks + tig]);
                a[i][1] = __float_as_uint(As[(m+8)*36 + ks + tig]);
                a[i][2] = __float_as_uint(As[m*36     + ks + tig + 4]);
                a[i][3] = __float_as_uint(As[(m+8)*36 + ks + tig + 4]);
            }
            #pragma unroll
            for (int j=0;j<4;j++){
                int n = wc*32 + j*8 + gid;
                bfr[j][0] = __float_as_uint(Bs[(ks+tig)*136   + n]);
                bfr[j][1] = __float_as_uint(Bs[(ks+tig+4)*136 + n]);
            }
            #pragma unroll
            for (int i=0;i<4;i++)
                #pragma unroll
                for (int j=0;j<4;j++)
                    MMA_TF32(acc[i][j], a[i], bfr[j]);
        }
    }
    // epilogue: scatter to (B,H,S,64)
    #pragma unroll
    for (int i=0;i<4;i++){
        int m  = m0 + wr*64 + i*16 + gid;
        int bb = m >> 10, s1 = m & 1023;
        #pragma unroll
        for (int j=0;j<4;j++){
            int nl = n0 + wc*32 + j*8 + 2*tig;
            int h = nl >> 6, d = nl & 63;
            size_t base = ((size_t)(bb*NH + h)*SEQ + s1)*HD + d;
            float2 v0 = make_float2(acc[i][j][0] + bias[nl], acc[i][j][1] + bias[nl+1]);
            *(float2*)(out + base) = v0;
            float2 v1 = make_float2(acc[i][j][2] + bias[nl], acc[i][j][3] + bias[nl+1]);
            *(float2*)(out + base + (size_t)8*HD) = v1;
        }
    }
}

// ---------------- Kernel 3: attention ---------------------------------------
#define QS_LD 68
#define KS_LD 68
#define VS_LD 72
#define PS_LD 132
#define ATTN_SMEM_FLOATS (128*QS_LD + 128*KS_LD + 128*VS_LD + 128*PS_LD + 256)
#define ATTN_SMEM_BYTES  (ATTN_SMEM_FLOATS*4)

__device__ __forceinline__ void compute_scores(const float* Qs, const float* Ks,
    float sacc[2][8][4], int wr, int wc, int gid, int tig)
{
    #pragma unroll
    for (int i=0;i<2;i++)
      #pragma unroll
      for (int j=0;j<8;j++)
        #pragma unroll
        for (int r=0;r<4;r++) sacc[i][j][r] = 0.f;
    #pragma unroll
    for (int ks = 0; ks < 64; ks += 8){
        unsigned a[2][4], bfr[8][2];
        #pragma unroll
        for (int i=0;i<2;i++){
            int m = wr*32 + i*16 + gid;
            a[i][0] = __float_as_uint(Qs[m*QS_LD     + ks + tig]);
            a[i][1] = __float_as_uint(Qs[(m+8)*QS_LD + ks + tig]);
            a[i][2] = __float_as_uint(Qs[m*QS_LD     + ks + tig + 4]);
            a[i][3] = __float_as_uint(Qs[(m+8)*QS_LD + ks + tig + 4]);
        }
        #pragma unroll
        for (int j=0;j<8;j++){
            int n = wc*64 + j*8 + gid;
            bfr[j][0] = __float_as_uint(Ks[n*KS_LD + ks + tig]);
            bfr[j][1] = __float_as_uint(Ks[n*KS_LD + ks + tig + 4]);
        }
        #pragma unroll
        for (int i=0;i<2;i++)
            #pragma unroll
            for (int j=0;j<8;j++)
                MMA_TF32(sacc[i][j], a[i], bfr[j]);
    }
}

__global__ void __launch_bounds__(256) attn_kernel(
    const float* __restrict__ x, const int* __restrict__ kvlen,
    float* __restrict__ seq, float* __restrict__ attn_out)
{
    extern __shared__ float sm[];
    float* Qs   = sm;
    float* Ks   = Qs + 128*QS_LD;
    float* Vs   = Ks + 128*KS_LD;
    float* Ps   = Vs + 128*VS_LD;
    float* rsum = Ps + 128*PS_LD;
    float* rinv = rsum + 128;

    int qt = blockIdx.x, bh = blockIdx.y;
    int b = bh >> 4, h = bh & 15;
    int len = kvlen[b];
    int tid = threadIdx.x, lane = tid & 31, wid = tid >> 5;
    int gid = lane >> 2, tig = lane & 3;
    int wr = wid >> 1, wc = wid & 1;     // warps 4x2: 32 rows x 64 cols
    int q_base = qt * 128;

    // load Q tile (tf32-rounded)
    const float* qp = g_q + ((size_t)bh << 16) + (size_t)q_base * 64;
    #pragma unroll
    for (int s = 0; s < 8; s++){
        int idx = tid + 256*s;
        int r = idx >> 4, c4 = idx & 15;
        float4 v = ((const float4*)qp)[idx];
        float* d = &Qs[r*QS_LD + c4*4];
        d[0]=tf32r(v.x); d[1]=tf32r(v.y); d[2]=tf32r(v.z); d[3]=tf32r(v.w);
    }
    if (tid < 128) rsum[tid] = 0.f;

    // -------- pass A: row sums of exp(scores) over causal+pad-valid keys ----
    float part[4] = {0.f, 0.f, 0.f, 0.f};
    for (int kt = 0; kt <= qt; kt++){
        __syncthreads();
        const float* kp = g_k + ((size_t)bh << 16) + (size_t)kt * 8192;
        #pragma unroll
        for (int s = 0; s < 8; s++){
            int idx = tid + 256*s;
            int r = idx >> 4, c4 = idx & 15;
            float4 v = ((const float4*)kp)[idx];
            float* d = &Ks[r*KS_LD + c4*4];
            d[0]=tf32r(v.x); d[1]=tf32r(v.y); d[2]=tf32r(v.z); d[3]=tf32r(v.w);
        }
        __syncthreads();
        float sacc[2][8][4];
        compute_scores(Qs, Ks, sacc, wr, wc, gid, tig);
        #pragma unroll
        for (int i=0;i<2;i++){
            int qr0 = q_base + wr*32 + i*16 + gid;
            int qr1 = qr0 + 8;
            #pragma unroll
            for (int j=0;j<8;j++){
                int c0 = kt*128 + wc*64 + j*8 + 2*tig;
                int c1 = c0 + 1;
                float p00 = (c0 <= qr0 && c0 < len) ? __expf(sacc[i][j][0]*0.125f) : 0.f;
                float p01 = (c1 <= qr0 && c1 < len) ? __expf(sacc[i][j][1]*0.125f) : 0.f;
                float p10 = (c0 <= qr1 && c0 < len) ? __expf(sacc[i][j][2]*0.125f) : 0.f;
                float p11 = (c1 <= qr1 && c1 < len) ? __expf(sacc[i][j][3]*0.125f) : 0.f;
                part[i*2+0] += p00 + p01;
                part[i*2+1] += p10 + p11;
            }
        }
    }
    #pragma unroll
    for (int pi = 0; pi < 4; pi++){
        float p = part[pi];
        p += __shfl_xor_sync(0xffffffffu, p, 1);
        p += __shfl_xor_sync(0xffffffffu, p, 2);
        if (tig == 0){
            int r = wr*32 + (pi >> 1)*16 + gid + (pi & 1)*8;
            atomicAdd(&rsum[r], p);
        }
    }
    __syncthreads();
    if (tid < 128) rinv[tid] = 1.0f / rsum[tid];

    // -------- pass B: normalized P -> attn out + O = P@V --------------------
    float oacc[2][4][4];
    #pragma unroll
    for (int i=0;i<2;i++)
      #pragma unroll
      for (int j=0;j<4;j++)
        #pragma unroll
        for (int r=0;r<4;r++) oacc[i][j][r] = 0.f;

    for (int kt = 0; kt < 8; kt++){
        float* aout = attn_out + ((size_t)bh << 20) + (size_t)q_base * 1024 + kt*128;
        if (kt > qt){   // fully-masked causal region: write zeros
            #pragma unroll
            for (int s = 0; s < 16; s++){
                int idx = tid + 256*s;
                int r = idx >> 5, c4 = idx & 31;
                *(float4*)(aout + (size_t)r*1024 + c4*4) = make_float4(0.f,0.f,0.f,0.f);
            }
            continue;
        }
        __syncthreads();
        const float* kp = g_k + ((size_t)bh << 16) + (size_t)kt * 8192;
        const float* vp = g_v + ((size_t)bh << 16) + (size_t)kt * 8192;
        #pragma unroll
        for (int s = 0; s < 8; s++){
            int idx = tid + 256*s;
            int r = idx >> 4, c4 = idx & 15;
            float4 v = ((const float4*)kp)[idx];
            float* d = &Ks[r*KS_LD + c4*4];
            d[0]=tf32r(v.x); d[1]=tf32r(v.y); d[2]=tf32r(v.z); d[3]=tf32r(v.w);
            float4 u = ((const float4*)vp)[idx];
            float* dv = &Vs[r*VS_LD + c4*4];
            dv[0]=tf32r(u.x); dv[1]=tf32r(u.y); dv[2]=tf32r(u.z); dv[3]=tf32r(u.w);
        }
        __syncthreads();
        float sacc[2][8][4];
        compute_scores(Qs, Ks, sacc, wr, wc, gid, tig);
        #pragma unroll
        for (int i=0;i<2;i++){
            int r0  = wr*32 + i*16 + gid;
            int qr0 = q_base + r0, qr1 = qr0 + 8;
            float inv0 = rinv[r0], inv1 = rinv[r0 + 8];
            #pragma unroll
            for (int j=0;j<8;j++){
                int cl = wc*64 + j*8 + 2*tig;
                int c0 = kt*128 + cl, c1 = c0 + 1;
                float p00 = (c0 <= qr0 && c0 < len) ? __expf(sacc[i][j][0]*0.125f)*inv0 : 0.f;
                float p01 = (c1 <= qr0 && c1 < len) ? __expf(sacc[i][j][1]*0.125f)*inv0 : 0.f;
                float p10 = (c0 <= qr1 && c0 < len) ? __expf(sacc[i][j][2]*0.125f)*inv1 : 0.f;
                float p11 = (c1 <= qr1 && c1 < len) ? __expf(sacc[i][j][3]*0.125f)*inv1 : 0.f;
                Ps[r0*PS_LD + cl]       = p00;
                Ps[r0*PS_LD + cl + 1]   = p01;
                Ps[(r0+8)*PS_LD + cl]   = p10;
                Ps[(r0+8)*PS_LD + cl+1] = p11;
            }
        }
        __syncthreads();
        // write normalized attn tile (coalesced float4)
        #pragma unroll
        for (int s = 0; s < 16; s++){
            int idx = tid + 256*s;
            int r = idx >> 5, c4 = idx & 31;
            float4 v = *(float4*)(&Ps[r*PS_LD + c4*4]);
            *(float4*)(aout + (size_t)r*1024 + c4*4) = v;
        }
        // O += P @ V   (128 keys, warps 4x2 over 128x64 O-tile)
        #pragma unroll
        for (int ks = 0; ks < 128; ks += 8){
            unsigned a[2][4], bfr[4][2];
            #pragma unroll
            for (int i=0;i<2;i++){
                int m = wr*32 + i*16 + gid;
                a[i][0] = __float_as_uint(tf32r(Ps[m*PS_LD     + ks + tig]));
                a[i][1] = __float_as_uint(tf32r(Ps[(m+8)*PS_LD + ks + tig]));
                a[i][2] = __float_as_uint(tf32r(Ps[m*PS_LD     + ks + tig + 4]));
                a[i][3] = __float_as_uint(tf32r(Ps[(m+8)*PS_LD + ks + tig + 4]));
            }
            #pragma unroll
            for (int j=0;j<4;j++){
                int n = wc*32 + j*8 + gid;
                bfr[j][0] = __float_as_uint(Vs[(ks+tig)*VS_LD   + n]);
                bfr[j][1] = __float_as_uint(Vs[(ks+tig+4)*VS_LD + n]);
            }
            #pragma unroll
            for (int i=0;i<2;i++)
                #pragma unroll
                for (int j=0;j<4;j++)
                    MMA_TF32(oacc[i][j], a[i], bfr[j]);
        }
    }
    // epilogue: seq = x + O (per-head 64-col slice)
    #pragma unroll
    for (int i=0;i<2;i++){
        int r0 = wr*32 + i*16 + gid;
        int q0 = q_base + r0;
        #pragma unroll
        for (int j=0;j<4;j++){
            int col = wc*32 + j*8 + 2*tig;
            size_t a0 = ((size_t)(b*SEQ + q0))*DMODEL + h*HD + col;
            float2 xa = *(const float2*)(x + a0);
            *(float2*)(seq + a0) = make_float2(xa.x + oacc[i][j][0], xa.y + oacc[i][j][1]);
            size_t a1 = a0 + (size_t)8*DMODEL;
            float2 xb = *(const float2*)(x + a1);
            *(float2*)(seq + a1) = make_float2(xb.x + oacc[i][j][2], xb.y + oacc[i][j][3]);
        }
    }
}

// ---------------- launch ----------------------------------------------------
extern "C" void kernel_launch(void* const* d_in, const int* in_sizes, int n_in,
                              void* d_out, int out_size)
{
    const float* x     = (const float*)d_in[0];
    const int*   kvlen = (const int*)  d_in[3];
    const float* gamma = (const float*)d_in[4];
    const float* beta  = (const float*)d_in[5];
    const float* Wq    = (const float*)d_in[6];
    const float* bq    = (const float*)d_in[7];
    const float* Wk    = (const float*)d_in[8];
    const float* bk    = (const float*)d_in[9];
    const float* Wv    = (const float*)d_in[10];
    const float* bv    = (const float*)d_in[11];

    float* seq  = (float*)d_out;
    float* attn = seq + (size_t)BATCH*SEQ*DMODEL;

    cudaFuncSetAttribute(attn_kernel,
        cudaFuncAttributeMaxDynamicSharedMemorySize, ATTN_SMEM_BYTES);

    ln_kernel<<<BATCH*SEQ, 256>>>(x, gamma, beta);
    proj_kernel<<<dim3(32, 24), 256>>>(Wq, bq, Wk, bk, Wv, bv);
    attn_kernel<<<dim3(8, 64), 256, ATTN_SMEM_BYTES>>>(x, kvlen, seq, attn);
}